// round 13
// baseline (speedup 1.0000x reference)
#include <cuda_runtime.h>
#include <cstdint>

// Fixed problem sizes (from reference setup_inputs)
#define NN   50000      // nodes
#define NE   150000     // edges
#define DD   512        // hidden dim
#define NL   4          // layers
#define NOUT 128        // output dim
#define F4   (DD/4)     // float4 per row = 128

typedef unsigned long long u64;

// ---------------- scratch (static device globals; no allocation) ----------
__device__ float g_h[(size_t)NN * DD];      // current node features
__device__ float g_z[(size_t)NN * DD];      // aggregation / gemm2 output
__device__ float g_y[(size_t)NN * DD];      // gemm1 output
__device__ float g_hsum[(size_t)NN * DD];   // hidden_sum accumulator
__device__ float g_t[(size_t)NE * DD];      // decoder intermediate [E,512]
__device__ float g_stats[2 * DD];           // per-feature sum / sumsq
__device__ int   g_degfill[2 * NN];         // [0,NN)=deg, [NN,2NN)=fill cursor
__device__ int   g_rowptr[NN + 1];
__device__ int   g_col[2 * NE];

// ---------------- packed fp32 helpers (sm_103a FFMA2 path) -----------------
__device__ __forceinline__ u64 bcast_f32x2(float x) {
    u64 r;
    asm("mov.b64 %0, {%1, %1};" : "=l"(r) : "r"(__float_as_uint(x)));
    return r;
}
#define FFMA_F32X2(acc, a, b) \
    asm("fma.rn.f32x2 %0, %1, %2, %0;" : "+l"(acc) : "l"(a), "l"(b))

// ---------------- small utility kernels -----------------------------------
__global__ void zero_ints(int* p, int n) {
    int i = blockIdx.x * blockDim.x + threadIdx.x;
    if (i < n) p[i] = 0;
}
__global__ void zero_floats(float* p, int n) {
    int i = blockIdx.x * blockDim.x + threadIdx.x;
    if (i < n) p[i] = 0.f;
}

// h = emb[h_ids]; hsum = h
__global__ void embed_kernel(const int* __restrict__ h_ids,
                             const float* __restrict__ emb,
                             float* __restrict__ h, float* __restrict__ hsum) {
    int i = blockIdx.x * blockDim.x + threadIdx.x;  // over NN*F4 float4s
    if (i >= NN * F4) return;
    int n = i >> 7;
    int f = i & 127;
    float4 v = ((const float4*)emb)[(size_t)h_ids[n] * F4 + f];
    ((float4*)h)[i] = v;
    ((float4*)hsum)[i] = v;
}

// ---------------- CSR build (graph is layer-invariant) ---------------------
__global__ void count_deg(const int* __restrict__ u, const int* __restrict__ v) {
    int e = blockIdx.x * blockDim.x + threadIdx.x;
    if (e < NE) {
        atomicAdd(&g_degfill[v[e]], 1);   // u -> v delivers to v
        atomicAdd(&g_degfill[u[e]], 1);   // v -> u delivers to u
    }
}

__global__ void scan_deg() {
    __shared__ int ps[512];
    const int t = threadIdx.x;
    const int CH = (NN + 511) / 512;  // 98
    int lo = t * CH;
    int hi = lo + CH; if (hi > NN) hi = NN;
    int s = 0;
    for (int r = lo; r < hi; ++r) s += g_degfill[r];
    ps[t] = s;
    __syncthreads();
    // Hillis-Steele inclusive scan over 512 partials
    for (int d = 1; d < 512; d <<= 1) {
        int o = (t >= d) ? ps[t - d] : 0;
        __syncthreads();
        ps[t] += o;
        __syncthreads();
    }
    int off = ps[t] - s;  // exclusive prefix
    for (int r = lo; r < hi; ++r) { g_rowptr[r] = off; off += g_degfill[r]; }
    if (hi == NN) g_rowptr[NN] = off;  // tail threads all hold the grand total
}

__global__ void fill_csr(const int* __restrict__ u, const int* __restrict__ v) {
    int e = blockIdx.x * blockDim.x + threadIdx.x;
    if (e < NE) {
        int a = u[e], b = v[e];
        int p = atomicAdd(&g_degfill[NN + b], 1);
        g_col[g_rowptr[b] + p] = a;
        int q = atomicAdd(&g_degfill[NN + a], 1);
        g_col[g_rowptr[a] + q] = b;
    }
}

// z[n] = 2*h[n] + sum_{j in adj(n)} h[j]     (self-loop folded into 2*h)
__global__ void aggregate(const float* __restrict__ h, float* __restrict__ z) {
    int n = blockIdx.x;       // one block per node
    int f = threadIdx.x;      // 128 threads, one float4 each
    const float4* hb = (const float4*)h;
    float4 acc = hb[(size_t)n * F4 + f];
    acc.x *= 2.f; acc.y *= 2.f; acc.z *= 2.f; acc.w *= 2.f;
    int lo = g_rowptr[n], hi = g_rowptr[n + 1];
    for (int p = lo; p < hi; ++p) {
        int j = g_col[p];
        float4 v = hb[(size_t)j * F4 + f];
        acc.x += v.x; acc.y += v.y; acc.z += v.z; acc.w += v.w;
    }
    ((float4*)z)[(size_t)n * F4 + f] = acc;
}

// ---------------- BatchNorm helpers ----------------------------------------
// Per-feature sum / sumsq partials; 512 blocks x 512 threads (thread = feature)
__global__ void bn_stats(const float* __restrict__ x, int M) {
    int c = threadIdx.x;
    float s = 0.f, sq = 0.f;
    for (int r = blockIdx.x; r < M; r += gridDim.x) {
        float v = x[(size_t)r * DD + c];
        s += v; sq += v * v;
    }
    atomicAdd(&g_stats[c], s);
    atomicAdd(&g_stats[DD + c], sq);
}

// x = relu(bn(x))  in place
__global__ void bn_relu(float* __restrict__ x,
                        const float* __restrict__ gam,
                        const float* __restrict__ bet, int M) {
    int i = blockIdx.x * blockDim.x + threadIdx.x;
    if (i >= M * DD) return;
    int c = i & (DD - 1);
    float inv_m = 1.f / (float)M;
    float mean = g_stats[c] * inv_m;
    float var = g_stats[DD + c] * inv_m - mean * mean;
    float val = (x[i] - mean) * rsqrtf(var + 1e-5f) * gam[c] + bet[c];
    x[i] = fmaxf(val, 0.f);
}

// h = relu(bn(zin)); hsum += h
__global__ void bn_relu_acc(const float* __restrict__ zin,
                            const float* __restrict__ gam,
                            const float* __restrict__ bet,
                            float* __restrict__ h, float* __restrict__ hsum, int M) {
    int i = blockIdx.x * blockDim.x + threadIdx.x;
    if (i >= M * DD) return;
    int c = i & (DD - 1);
    float inv_m = 1.f / (float)M;
    float mean = g_stats[c] * inv_m;
    float var = g_stats[DD + c] * inv_m - mean * mean;
    float val = (zin[i] - mean) * rsqrtf(var + 1e-5f) * gam[c] + bet[c];
    val = fmaxf(val, 0.f);
    h[i] = val;
    hsum[i] += val;
}

// ---------------- SGEMM: 128x128x8 tile, 256 threads, 8x8 per thread -------
// Double-buffered smem; inner product uses packed fp32 FFMA2 (fma.rn.f32x2):
// accumulators hold column pairs, A value broadcast into both lanes.
// C[M, Ncols] = op(A) @ B (+bias)(relu). B row-major [K, Ncols].
// GATHER=1: A rows are concat(hsum[u[r]], hsum[v[r]]) with K=1024, row stride 512.
template <int GATHER, int BIAS, int RELU>
__global__ void __launch_bounds__(256)
sgemm(const float* __restrict__ A, const float* __restrict__ B,
      float* __restrict__ C, const float* __restrict__ bias,
      const int* __restrict__ iu, const int* __restrict__ iv,
      int M, int Ncols, int K)
{
    __shared__ __align__(16) float As[2][8][128];
    __shared__ __align__(16) float Bs[2][8][128];
    __shared__ int su[128], sv[128];

    const int tid  = threadIdx.x;
    const int brow = blockIdx.x, bcol = blockIdx.y;
    const int tx = tid & 15, ty = tid >> 4;

    const int a_r = tid >> 1;          // 0..127
    const int a_c = (tid & 1) * 4;     // 0 or 4
    const int b_r = tid >> 5;          // 0..7
    const int b_c = (tid & 31) * 4;    // 0..124
    const int grow = brow * 128 + a_r;

    if (GATHER) {
        // 256 threads: first 128 load su, next 128 load sv
        int li = tid & 127;
        int r = brow * 128 + li;
        int idx = (r < M) ? ((tid < 128) ? iu[r] : iv[r]) : 0;
        if (tid < 128) su[li] = idx; else sv[li] = idx;
        __syncthreads();
    }

    // acc2[i][jj] holds C(row ty*8+i, cols tx*8+2jj .. +2jj+1) as packed f32x2
    u64 acc2[8][4];
#pragma unroll
    for (int i = 0; i < 8; i++)
#pragma unroll
        for (int j = 0; j < 4; j++) acc2[i][j] = 0ull;

    // ---- tile loaders (into registers) ----
    auto loadA = [&](int k0) -> float4 {
        float4 av = make_float4(0.f, 0.f, 0.f, 0.f);
        if (grow < M) {
            int kk = k0 + a_c;
            if (GATHER) {
                int node = (kk < 512) ? su[a_r] : sv[a_r];
                av = *(const float4*)(A + (size_t)node * 512 + (kk & 511));
            } else {
                av = *(const float4*)(A + (size_t)grow * K + kk);
            }
        }
        return av;
    };
    auto loadB = [&](int k0) -> float4 {
        return *(const float4*)(B + (size_t)(k0 + b_r) * Ncols + bcol * 128 + b_c);
    };

    // preload tile 0 into buffer 0
    {
        float4 av = loadA(0);
        float4 bv = loadB(0);
        As[0][a_c + 0][a_r] = av.x;
        As[0][a_c + 1][a_r] = av.y;
        As[0][a_c + 2][a_r] = av.z;
        As[0][a_c + 3][a_r] = av.w;
        *(float4*)&Bs[0][b_r][b_c] = bv;
    }
    __syncthreads();

    const int ntiles = K >> 3;
    for (int t0 = 0; t0 < ntiles; ++t0) {
        const int cur = t0 & 1;
        float4 av, bv;
        const bool more = (t0 + 1 < ntiles);
        if (more) {                 // issue next-tile global loads early
            av = loadA((t0 + 1) << 3);
            bv = loadB((t0 + 1) << 3);
        }
#pragma unroll
        for (int kk = 0; kk < 8; ++kk) {
            float4 a0 = *(const float4*)&As[cur][kk][ty * 8];
            float4 a1 = *(const float4*)&As[cur][kk][ty * 8 + 4];
            // B columns as natural packed pairs (contiguous in smem)
            ulonglong2 bq0 = *(const ulonglong2*)&Bs[cur][kk][tx * 8];
            ulonglong2 bq1 = *(const ulonglong2*)&Bs[cur][kk][tx * 8 + 4];
            u64 bb[4] = {bq0.x, bq0.y, bq1.x, bq1.y};
            float ar[8] = {a0.x, a0.y, a0.z, a0.w, a1.x, a1.y, a1.z, a1.w};
#pragma unroll
            for (int i = 0; i < 8; i++) {
                u64 ap = bcast_f32x2(ar[i]);
#pragma unroll
                for (int j = 0; j < 4; j++)
                    FFMA_F32X2(acc2[i][j], ap, bb[j]);
            }
        }
        if (more) {
            const int nxt = cur ^ 1;
            As[nxt][a_c + 0][a_r] = av.x;
            As[nxt][a_c + 1][a_r] = av.y;
            As[nxt][a_c + 2][a_r] = av.z;
            As[nxt][a_c + 3][a_r] = av.w;
            *(float4*)&Bs[nxt][b_r][b_c] = bv;
            __syncthreads();
        }
    }

#pragma unroll
    for (int i = 0; i < 8; i++) {
        int r = brow * 128 + ty * 8 + i;
        if (r >= M) continue;
#pragma unroll
        for (int j = 0; j < 4; j++) {
            unsigned int lo, hi;
            asm("mov.b64 {%0, %1}, %2;" : "=r"(lo), "=r"(hi) : "l"(acc2[i][j]));
            float v0 = __uint_as_float(lo);
            float v1 = __uint_as_float(hi);
            int c = bcol * 128 + tx * 8 + 2 * j;
            if (BIAS) { v0 += bias[c]; v1 += bias[c + 1]; }
            if (RELU) { v0 = fmaxf(v0, 0.f); v1 = fmaxf(v1, 0.f); }
            C[(size_t)r * Ncols + c]     = v0;
            C[(size_t)r * Ncols + c + 1] = v1;
        }
    }
}

// ---------------- launch ----------------------------------------------------
extern "C" void kernel_launch(void* const* d_in, const int* in_sizes, int n_in,
                              void* d_out, int out_size) {
    (void)in_sizes; (void)n_in; (void)out_size;
    const int*   h_ids = (const int*)d_in[0];
    const int*   u     = (const int*)d_in[1];
    const int*   v     = (const int*)d_in[2];
    const float* emb   = (const float*)d_in[3];
    const float* lin1  = (const float*)d_in[4];
    const float* lin2  = (const float*)d_in[5];
    const float* bn1g  = (const float*)d_in[6];
    const float* bn1b  = (const float*)d_in[7];
    const float* bn2g  = (const float*)d_in[8];
    const float* bn2b  = (const float*)d_in[9];
    const float* W1w   = (const float*)d_in[10];
    const float* W1b   = (const float*)d_in[11];
    const float* W2w   = (const float*)d_in[12];
    const float* W2b   = (const float*)d_in[13];
    float* out = (float*)d_out;

    float *h, *z, *y, *hsum, *t, *stats;
    int *degfill;
    cudaGetSymbolAddress((void**)&h,       g_h);
    cudaGetSymbolAddress((void**)&z,       g_z);
    cudaGetSymbolAddress((void**)&y,       g_y);
    cudaGetSymbolAddress((void**)&hsum,    g_hsum);
    cudaGetSymbolAddress((void**)&t,       g_t);
    cudaGetSymbolAddress((void**)&stats,   g_stats);
    cudaGetSymbolAddress((void**)&degfill, g_degfill);

    // --- build CSR for the symmetrized edge set (graph fixed across layers)
    zero_ints<<<(2 * NN + 255) / 256, 256>>>(degfill, 2 * NN);
    count_deg<<<(NE + 255) / 256, 256>>>(u, v);
    scan_deg<<<1, 512>>>();
    fill_csr<<<(NE + 255) / 256, 256>>>(u, v);

    // --- embedding lookup + hidden_sum init
    embed_kernel<<<(NN * F4 + 255) / 256, 256>>>(h_ids, emb, h, hsum);

    const dim3 gNode((NN + 127) / 128, DD / 128);   // 391 x 4
    const int  elemGrid = (NN * DD + 255) / 256;

    for (int i = 0; i < NL; ++i) {
        // z = 2h + neighbor sums
        aggregate<<<NN, 128>>>(h, z);
        // y = z @ lin1[i]
        sgemm<0, 0, 0><<<gNode, 256>>>(z, lin1 + (size_t)i * DD * DD, y,
                                       nullptr, nullptr, nullptr, NN, DD, DD);
        // BN1 + relu (in place on y)
        zero_floats<<<4, 256>>>(stats, 2 * DD);
        bn_stats<<<512, 512>>>(y, NN);
        bn_relu<<<elemGrid, 256>>>(y, bn1g + (size_t)i * DD, bn1b + (size_t)i * DD, NN);
        // z = y @ lin2[i]   (reuse z)
        sgemm<0, 0, 0><<<gNode, 256>>>(y, lin2 + (size_t)i * DD * DD, z,
                                       nullptr, nullptr, nullptr, NN, DD, DD);
        // h = relu(BN2(z)); hsum += h
        zero_floats<<<4, 256>>>(stats, 2 * DD);
        bn_stats<<<512, 512>>>(z, NN);
        bn_relu_acc<<<elemGrid, 256>>>(z, bn2g + (size_t)i * DD, bn2b + (size_t)i * DD,
                                       h, hsum, NN);
    }

    // --- decoder: t = relu([hsum[u] ‖ hsum[v]] @ W1 + b1)
    const dim3 gDec1((NE + 127) / 128, DD / 128);   // 1172 x 4
    sgemm<1, 1, 1><<<gDec1, 256>>>(hsum, W1w, t, W1b, u, v, NE, DD, 2 * DD);
    // --- out = t @ W2 + b2
    const dim3 gDec2((NE + 127) / 128, NOUT / 128); // 1172 x 1
    sgemm<0, 1, 0><<<gDec2, 256>>>(t, W2w, out, W2b, nullptr, nullptr, NE, NOUT, DD);
}

// round 17
// speedup vs baseline: 1.5190x; 1.5190x over previous
#include <cuda_runtime.h>
#include <cstdint>

// Fixed problem sizes (from reference setup_inputs)
#define NN   50000      // nodes
#define NE   150000     // edges
#define DD   512        // hidden dim
#define NL   4          // layers
#define NOUT 128        // output dim
#define F4   (DD/4)     // float4 per row = 128

// ---------------- scratch (static device globals; no allocation) ----------
__device__ float g_h[(size_t)NN * DD];      // current node features
__device__ float g_z[(size_t)NN * DD];      // aggregation / gemm2 output
__device__ float g_y[(size_t)NN * DD];      // gemm1 output
__device__ float g_hsum[(size_t)NN * DD];   // hidden_sum accumulator
__device__ float g_t[(size_t)NE * DD];      // decoder intermediate [E,512]
__device__ float g_stats[2 * DD];           // per-feature sum / sumsq
__device__ int   g_degfill[2 * NN];         // [0,NN)=deg, [NN,2NN)=fill cursor
__device__ int   g_rowptr[NN + 1];
__device__ int   g_col[2 * NE];

// ---------------- tf32 helpers ---------------------------------------------
__device__ __forceinline__ uint32_t f2tf32(float x) {
    uint32_t r;
    asm("cvt.rna.tf32.f32 %0, %1;" : "=r"(r) : "f"(x));
    return r;
}
#define MMA_TF32(d, a0, a1, a2, a3, b0, b1)                                   \
    asm volatile("mma.sync.aligned.m16n8k8.row.col.f32.tf32.tf32.f32 "        \
                 "{%0,%1,%2,%3}, {%4,%5,%6,%7}, {%8,%9}, {%0,%1,%2,%3};"      \
                 : "+f"(d[0]), "+f"(d[1]), "+f"(d[2]), "+f"(d[3])             \
                 : "r"(a0), "r"(a1), "r"(a2), "r"(a3), "r"(b0), "r"(b1))

// ---------------- small utility kernels -----------------------------------
__global__ void zero_ints(int* p, int n) {
    int i = blockIdx.x * blockDim.x + threadIdx.x;
    if (i < n) p[i] = 0;
}
__global__ void zero_floats(float* p, int n) {
    int i = blockIdx.x * blockDim.x + threadIdx.x;
    if (i < n) p[i] = 0.f;
}

// h = emb[h_ids]; hsum = h
__global__ void embed_kernel(const int* __restrict__ h_ids,
                             const float* __restrict__ emb,
                             float* __restrict__ h, float* __restrict__ hsum) {
    int i = blockIdx.x * blockDim.x + threadIdx.x;  // over NN*F4 float4s
    if (i >= NN * F4) return;
    int n = i >> 7;
    int f = i & 127;
    float4 v = ((const float4*)emb)[(size_t)h_ids[n] * F4 + f];
    ((float4*)h)[i] = v;
    ((float4*)hsum)[i] = v;
}

// ---------------- CSR build (graph is layer-invariant) ---------------------
__global__ void count_deg(const int* __restrict__ u, const int* __restrict__ v) {
    int e = blockIdx.x * blockDim.x + threadIdx.x;
    if (e < NE) {
        atomicAdd(&g_degfill[v[e]], 1);   // u -> v delivers to v
        atomicAdd(&g_degfill[u[e]], 1);   // v -> u delivers to u
    }
}

__global__ void scan_deg() {
    __shared__ int ps[512];
    const int t = threadIdx.x;
    const int CH = (NN + 511) / 512;  // 98
    int lo = t * CH;
    int hi = lo + CH; if (hi > NN) hi = NN;
    int s = 0;
    for (int r = lo; r < hi; ++r) s += g_degfill[r];
    ps[t] = s;
    __syncthreads();
    // Hillis-Steele inclusive scan over 512 partials
    for (int d = 1; d < 512; d <<= 1) {
        int o = (t >= d) ? ps[t - d] : 0;
        __syncthreads();
        ps[t] += o;
        __syncthreads();
    }
    int off = ps[t] - s;  // exclusive prefix
    for (int r = lo; r < hi; ++r) { g_rowptr[r] = off; off += g_degfill[r]; }
    if (hi == NN) g_rowptr[NN] = off;  // tail threads all hold the grand total
}

__global__ void fill_csr(const int* __restrict__ u, const int* __restrict__ v) {
    int e = blockIdx.x * blockDim.x + threadIdx.x;
    if (e < NE) {
        int a = u[e], b = v[e];
        int p = atomicAdd(&g_degfill[NN + b], 1);
        g_col[g_rowptr[b] + p] = a;
        int q = atomicAdd(&g_degfill[NN + a], 1);
        g_col[g_rowptr[a] + q] = b;
    }
}

// z[n] = 2*h[n] + sum_{j in adj(n)} h[j]     (self-loop folded into 2*h)
__global__ void aggregate(const float* __restrict__ h, float* __restrict__ z) {
    int n = blockIdx.x;       // one block per node
    int f = threadIdx.x;      // 128 threads, one float4 each
    const float4* hb = (const float4*)h;
    float4 acc = hb[(size_t)n * F4 + f];
    acc.x *= 2.f; acc.y *= 2.f; acc.z *= 2.f; acc.w *= 2.f;
    int lo = g_rowptr[n], hi = g_rowptr[n + 1];
    for (int p = lo; p < hi; ++p) {
        int j = g_col[p];
        float4 v = hb[(size_t)j * F4 + f];
        acc.x += v.x; acc.y += v.y; acc.z += v.z; acc.w += v.w;
    }
    ((float4*)z)[(size_t)n * F4 + f] = acc;
}

// ---------------- BatchNorm helpers ----------------------------------------
__global__ void bn_stats(const float* __restrict__ x, int M) {
    int c = threadIdx.x;
    float s = 0.f, sq = 0.f;
    for (int r = blockIdx.x; r < M; r += gridDim.x) {
        float v = x[(size_t)r * DD + c];
        s += v; sq += v * v;
    }
    atomicAdd(&g_stats[c], s);
    atomicAdd(&g_stats[DD + c], sq);
}

__global__ void bn_relu(float* __restrict__ x,
                        const float* __restrict__ gam,
                        const float* __restrict__ bet, int M) {
    int i = blockIdx.x * blockDim.x + threadIdx.x;
    if (i >= M * DD) return;
    int c = i & (DD - 1);
    float inv_m = 1.f / (float)M;
    float mean = g_stats[c] * inv_m;
    float var = g_stats[DD + c] * inv_m - mean * mean;
    float val = (x[i] - mean) * rsqrtf(var + 1e-5f) * gam[c] + bet[c];
    x[i] = fmaxf(val, 0.f);
}

__global__ void bn_relu_acc(const float* __restrict__ zin,
                            const float* __restrict__ gam,
                            const float* __restrict__ bet,
                            float* __restrict__ h, float* __restrict__ hsum, int M) {
    int i = blockIdx.x * blockDim.x + threadIdx.x;
    if (i >= M * DD) return;
    int c = i & (DD - 1);
    float inv_m = 1.f / (float)M;
    float mean = g_stats[c] * inv_m;
    float var = g_stats[DD + c] * inv_m - mean * mean;
    float val = (zin[i] - mean) * rsqrtf(var + 1e-5f) * gam[c] + bet[c];
    val = fmaxf(val, 0.f);
    h[i] = val;
    hsum[i] += val;
}

// ---------------- Tensor-core GEMM: 128x128x16 tiles, 3xTF32 split ---------
// C[M, Ncols] = A @ B (+bias)(relu), fp32 in/out, tf32 hi/lo split inside.
// 8 warps, each computes a 64x32 warp tile via m16n8k8 mma.sync.
// Smem stride 136: fragment LDS bank = (8*tg + gid) % 32 -> conflict-free.
// GATHER=1: A rows are concat(hsum[u[r]], hsum[v[r]]), K=1024, row stride 512.
template <int GATHER, int BIAS, int RELU>
__global__ void __launch_bounds__(256)
sgemm_tc(const float* __restrict__ A, const float* __restrict__ B,
         float* __restrict__ C, const float* __restrict__ bias,
         const int* __restrict__ iu, const int* __restrict__ iv,
         int M, int Ncols, int K)
{
    constexpr int S = 136;
    __shared__ uint32_t sAhi[16][S], sAlo[16][S];   // [k][m]
    __shared__ uint32_t sBhi[16][S], sBlo[16][S];   // [k][n]
    __shared__ int su[128], sv[128];

    const int tid  = threadIdx.x;
    const int brow = blockIdx.x, bcol = blockIdx.y;
    const int lane = tid & 31, warp = tid >> 5;
    const int gid  = lane >> 2, tg = lane & 3;
    const int moff = (warp >> 2) * 64;   // warp row offset in tile
    const int noff = (warp & 3) * 32;    // warp col offset in tile

    if (GATHER) {
        int li = tid & 127;
        int r = brow * 128 + li;
        int idx = (r < M) ? ((tid < 128) ? iu[r] : iv[r]) : 0;
        if (tid < 128) su[li] = idx; else sv[li] = idx;
        __syncthreads();
    }

    float acc[16][4];
#pragma unroll
    for (int i = 0; i < 16; i++)
#pragma unroll
        for (int j = 0; j < 4; j++) acc[i][j] = 0.f;

    const int ntiles = K >> 4;
    for (int kt = 0; kt < ntiles; ++kt) {
        const int k0 = kt << 4;

        // ---- stage A tile [128 rows x 16 k] as hi/lo tf32, layout [k][m]
#pragma unroll
        for (int f = tid; f < 512; f += 256) {
            int row = f >> 2;
            int cq  = (f & 3) << 2;          // k-offset within tile: 0,4,8,12
            float4 val = make_float4(0.f, 0.f, 0.f, 0.f);
            int gr = brow * 128 + row;
            if (gr < M) {
                int kk = k0 + cq;
                const float* src;
                if (GATHER) {
                    int node = (kk < 512) ? su[row] : sv[row];
                    src = A + (size_t)node * 512 + (kk & 511);
                } else {
                    src = A + (size_t)gr * K + kk;
                }
                val = *(const float4*)src;
            }
            float xs[4] = {val.x, val.y, val.z, val.w};
#pragma unroll
            for (int i = 0; i < 4; i++) {
                uint32_t hi = f2tf32(xs[i]);
                uint32_t lo = f2tf32(xs[i] - __uint_as_float(hi));
                sAhi[cq + i][row] = hi;
                sAlo[cq + i][row] = lo;
            }
        }

        // ---- stage B tile [16 k x 128 cols] as hi/lo tf32, layout [k][n]
#pragma unroll
        for (int f = tid; f < 512; f += 256) {
            int rk  = f >> 5;                // 0..15
            int col = (f & 31) << 2;         // 0..124
            float4 val = *(const float4*)(B + (size_t)(k0 + rk) * Ncols
                                          + bcol * 128 + col);
            uint32_t h0 = f2tf32(val.x), h1 = f2tf32(val.y),
                     h2 = f2tf32(val.z), h3 = f2tf32(val.w);
            uint32_t l0 = f2tf32(val.x - __uint_as_float(h0));
            uint32_t l1 = f2tf32(val.y - __uint_as_float(h1));
            uint32_t l2 = f2tf32(val.z - __uint_as_float(h2));
            uint32_t l3 = f2tf32(val.w - __uint_as_float(h3));
            *(uint4*)&sBhi[rk][col] = make_uint4(h0, h1, h2, h3);
            *(uint4*)&sBlo[rk][col] = make_uint4(l0, l1, l2, l3);
        }
        __syncthreads();

        // ---- compute: 2 k8 steps, 4 m-tiles x 4 n-tiles x 3 MMAs
#pragma unroll
        for (int kk = 0; kk < 16; kk += 8) {
            uint32_t bh0[4], bh1[4], bl0[4], bl1[4];
#pragma unroll
            for (int nt = 0; nt < 4; nt++) {
                int cb = noff + nt * 8 + gid;
                bh0[nt] = sBhi[kk + tg][cb];
                bh1[nt] = sBhi[kk + tg + 4][cb];
                bl0[nt] = sBlo[kk + tg][cb];
                bl1[nt] = sBlo[kk + tg + 4][cb];
            }
#pragma unroll
            for (int mt = 0; mt < 4; mt++) {
                int r0 = moff + mt * 16 + gid, r1 = r0 + 8;
                uint32_t ah0 = sAhi[kk + tg][r0],     ah1 = sAhi[kk + tg][r1];
                uint32_t ah2 = sAhi[kk + tg + 4][r0], ah3 = sAhi[kk + tg + 4][r1];
                uint32_t al0 = sAlo[kk + tg][r0],     al1 = sAlo[kk + tg][r1];
                uint32_t al2 = sAlo[kk + tg + 4][r0], al3 = sAlo[kk + tg + 4][r1];
#pragma unroll
                for (int nt = 0; nt < 4; nt++) {
                    float* d = acc[mt * 4 + nt];
                    MMA_TF32(d, ah0, ah1, ah2, ah3, bh0[nt], bh1[nt]);
                    MMA_TF32(d, al0, al1, al2, al3, bh0[nt], bh1[nt]);
                    MMA_TF32(d, ah0, ah1, ah2, ah3, bl0[nt], bl1[nt]);
                }
            }
        }
        __syncthreads();
    }

    // ---- epilogue
#pragma unroll
    for (int mt = 0; mt < 4; mt++) {
#pragma unroll
        for (int nt = 0; nt < 4; nt++) {
            const float* d = acc[mt * 4 + nt];
            int gr0 = brow * 128 + moff + mt * 16 + gid;
            int gc  = bcol * 128 + noff + nt * 8 + 2 * tg;
            float c0 = d[0], c1 = d[1], c2 = d[2], c3 = d[3];
            if (BIAS) {
                float b0 = bias[gc], b1 = bias[gc + 1];
                c0 += b0; c1 += b1; c2 += b0; c3 += b1;
            }
            if (RELU) {
                c0 = fmaxf(c0, 0.f); c1 = fmaxf(c1, 0.f);
                c2 = fmaxf(c2, 0.f); c3 = fmaxf(c3, 0.f);
            }
            if (gr0 < M) {
                float2 w0 = make_float2(c0, c1);
                *(float2*)&C[(size_t)gr0 * Ncols + gc] = w0;
            }
            if (gr0 + 8 < M) {
                float2 w1 = make_float2(c2, c3);
                *(float2*)&C[(size_t)(gr0 + 8) * Ncols + gc] = w1;
            }
        }
    }
}

// ---------------- launch ----------------------------------------------------
extern "C" void kernel_launch(void* const* d_in, const int* in_sizes, int n_in,
                              void* d_out, int out_size) {
    (void)in_sizes; (void)n_in; (void)out_size;
    const int*   h_ids = (const int*)d_in[0];
    const int*   u     = (const int*)d_in[1];
    const int*   v     = (const int*)d_in[2];
    const float* emb   = (const float*)d_in[3];
    const float* lin1  = (const float*)d_in[4];
    const float* lin2  = (const float*)d_in[5];
    const float* bn1g  = (const float*)d_in[6];
    const float* bn1b  = (const float*)d_in[7];
    const float* bn2g  = (const float*)d_in[8];
    const float* bn2b  = (const float*)d_in[9];
    const float* W1w   = (const float*)d_in[10];
    const float* W1b   = (const float*)d_in[11];
    const float* W2w   = (const float*)d_in[12];
    const float* W2b   = (const float*)d_in[13];
    float* out = (float*)d_out;

    float *h, *z, *y, *hsum, *t, *stats;
    int *degfill;
    cudaGetSymbolAddress((void**)&h,       g_h);
    cudaGetSymbolAddress((void**)&z,       g_z);
    cudaGetSymbolAddress((void**)&y,       g_y);
    cudaGetSymbolAddress((void**)&hsum,    g_hsum);
    cudaGetSymbolAddress((void**)&t,       g_t);
    cudaGetSymbolAddress((void**)&stats,   g_stats);
    cudaGetSymbolAddress((void**)&degfill, g_degfill);

    // --- build CSR for the symmetrized edge set (graph fixed across layers)
    zero_ints<<<(2 * NN + 255) / 256, 256>>>(degfill, 2 * NN);
    count_deg<<<(NE + 255) / 256, 256>>>(u, v);
    scan_deg<<<1, 512>>>();
    fill_csr<<<(NE + 255) / 256, 256>>>(u, v);

    // --- embedding lookup + hidden_sum init
    embed_kernel<<<(NN * F4 + 255) / 256, 256>>>(h_ids, emb, h, hsum);

    const dim3 gNode((NN + 127) / 128, DD / 128);   // 391 x 4
    const int  elemGrid = (NN * DD + 255) / 256;

    for (int i = 0; i < NL; ++i) {
        // z = 2h + neighbor sums
        aggregate<<<NN, 128>>>(h, z);
        // y = z @ lin1[i]
        sgemm_tc<0, 0, 0><<<gNode, 256>>>(z, lin1 + (size_t)i * DD * DD, y,
                                          nullptr, nullptr, nullptr, NN, DD, DD);
        // BN1 + relu (in place on y)
        zero_floats<<<4, 256>>>(stats, 2 * DD);
        bn_stats<<<512, 512>>>(y, NN);
        bn_relu<<<elemGrid, 256>>>(y, bn1g + (size_t)i * DD, bn1b + (size_t)i * DD, NN);
        // z = y @ lin2[i]   (reuse z)
        sgemm_tc<0, 0, 0><<<gNode, 256>>>(y, lin2 + (size_t)i * DD * DD, z,
                                          nullptr, nullptr, nullptr, NN, DD, DD);
        // h = relu(BN2(z)); hsum += h
        zero_floats<<<4, 256>>>(stats, 2 * DD);
        bn_stats<<<512, 512>>>(z, NN);
        bn_relu_acc<<<elemGrid, 256>>>(z, bn2g + (size_t)i * DD, bn2b + (size_t)i * DD,
                                       h, hsum, NN);
    }

    // --- decoder: t = relu([hsum[u] ‖ hsum[v]] @ W1 + b1)
    const dim3 gDec1((NE + 127) / 128, DD / 128);   // 1172 x 4
    sgemm_tc<1, 1, 1><<<gDec1, 256>>>(hsum, W1w, t, W1b, u, v, NE, DD, 2 * DD);
    // --- out = t @ W2 + b2
    const dim3 gDec2((NE + 127) / 128, NOUT / 128); // 1172 x 1
    sgemm_tc<0, 1, 0><<<gDec2, 256>>>(t, W2w, out, W2b, nullptr, nullptr, NE, NOUT, DD);
}